// round 2
// baseline (speedup 1.0000x reference)
#include <cuda_runtime.h>

// InducingLocationsSpatialTransform: bilinear affine warp
// X: (N=512, H=64, W=64, C=32) f32, theta: (N, 6) f32 -> out: (N,H,W,C) f32
// 8 threads per output pixel, float4 per thread (C=32 -> 8 x float4).

#define N_ 512
#define H_ 64
#define W_ 64
#define C_ 32
#define HW_ (H_ * W_)

__global__ __launch_bounds__(256) void st_kernel(
    const float* __restrict__ X,
    const float* __restrict__ theta,
    float* __restrict__ out)
{
    int tid = blockIdx.x * blockDim.x + threadIdx.x;
    int pid = tid >> 3;        // global pixel id in [0, N*H*W)
    int cg  = tid & 7;         // float4 group within the 32 channels

    int n = pid >> 12;         // pid / 4096
    int p = pid & 4095;
    int y = p >> 6;
    int x = p & 63;

    const float* th = theta + n * 6;
    float t0 = __ldg(th + 0), t1 = __ldg(th + 1), t2 = __ldg(th + 2);
    float t3 = __ldg(th + 3), t4 = __ldg(th + 4), t5 = __ldg(th + 5);

    const float step = 2.0f / 63.0f;
    float xt = -1.0f + (float)x * step;
    float yt = -1.0f + (float)y * step;

    float gxs = t0 * xt + t1 * yt + t2;   // source x in [-1,1] space
    float gys = t3 * xt + t4 * yt + t5;

    float gx = (float)W_ * (gxs + 1.0f) * 0.5f;
    float gy = (float)H_ * (gys + 1.0f) * 0.5f;

    float fx = floorf(gx);
    float fy = floorf(gy);

    int x0 = min(max((int)fx,     0), W_ - 1);
    int x1 = min(max((int)fx + 1, 0), W_ - 1);
    int y0 = min(max((int)fy,     0), H_ - 1);
    int y1 = min(max((int)fy + 1, 0), H_ - 1);

    // Weights from CLIPPED corner indices (matches reference semantics).
    float wa = ((float)x1 - gx) * ((float)y1 - gy);
    float wb = ((float)x1 - gx) * (gy - (float)y0);
    float wc = (gx - (float)x0) * ((float)y1 - gy);
    float wd = (gx - (float)x0) * (gy - (float)y0);

    const float4* S = (const float4*)(X + (size_t)n * HW_ * C_);
    // each pixel = 8 float4s
    float4 va = __ldg(&S[(y0 * W_ + x0) * 8 + cg]);
    float4 vb = __ldg(&S[(y1 * W_ + x0) * 8 + cg]);
    float4 vc = __ldg(&S[(y0 * W_ + x1) * 8 + cg]);
    float4 vd = __ldg(&S[(y1 * W_ + x1) * 8 + cg]);

    float4 r;
    r.x = wa * va.x + wb * vb.x + wc * vc.x + wd * vd.x;
    r.y = wa * va.y + wb * vb.y + wc * vc.y + wd * vd.y;
    r.z = wa * va.z + wb * vb.z + wc * vc.z + wd * vd.z;
    r.w = wa * va.w + wb * vb.w + wc * vc.w + wd * vd.w;

    ((float4*)out)[(size_t)pid * 8 + cg] = r;
}

extern "C" void kernel_launch(void* const* d_in, const int* in_sizes, int n_in,
                              void* d_out, int out_size)
{
    const float* X     = (const float*)d_in[0];
    const float* theta = (const float*)d_in[1];
    float* out         = (float*)d_out;

    // total threads = N*H*W*8 = 16,777,216
    int threads = 256;
    int blocks = (N_ * HW_ * 8) / threads;   // 65536
    st_kernel<<<blocks, threads>>>(X, theta, out);
}

// round 3
// speedup vs baseline: 1.0915x; 1.0915x over previous
#include <cuda_runtime.h>

// InducingLocationsSpatialTransform: bilinear affine warp
// X: (N=512, H=64, W=64, C=32) f32, theta: (N, 6) f32 -> out: (N,H,W,C) f32
// 4 threads per output pixel; each thread handles 2 float4 channel-groups
// (cg and cg+4), giving 8 independent gather loads in flight per thread.

#define N_ 512
#define H_ 64
#define W_ 64
#define C_ 32
#define HW_ (H_ * W_)

__global__ __launch_bounds__(256) void st_kernel(
    const float* __restrict__ X,
    const float* __restrict__ theta,
    float* __restrict__ out)
{
    int tid = blockIdx.x * blockDim.x + threadIdx.x;
    int pid = tid >> 2;        // global pixel id in [0, N*H*W)
    int cg  = tid & 3;         // first float4 group; second is cg+4

    int n = pid >> 12;         // pid / 4096
    int p = pid & 4095;
    int y = p >> 6;
    int x = p & 63;

    const float* th = theta + n * 6;
    float t0 = __ldg(th + 0), t1 = __ldg(th + 1), t2 = __ldg(th + 2);
    float t3 = __ldg(th + 3), t4 = __ldg(th + 4), t5 = __ldg(th + 5);

    const float step = 2.0f / 63.0f;
    float xt = -1.0f + (float)x * step;
    float yt = -1.0f + (float)y * step;

    float gxs = t0 * xt + t1 * yt + t2;
    float gys = t3 * xt + t4 * yt + t5;

    float gx = (float)W_ * (gxs + 1.0f) * 0.5f;
    float gy = (float)H_ * (gys + 1.0f) * 0.5f;

    float fx = floorf(gx);
    float fy = floorf(gy);

    int x0 = min(max((int)fx,     0), W_ - 1);
    int x1 = min(max((int)fx + 1, 0), W_ - 1);
    int y0 = min(max((int)fy,     0), H_ - 1);
    int y1 = min(max((int)fy + 1, 0), H_ - 1);

    // Weights from CLIPPED corner indices (matches reference semantics).
    float wa = ((float)x1 - gx) * ((float)y1 - gy);
    float wb = ((float)x1 - gx) * (gy - (float)y0);
    float wc = (gx - (float)x0) * ((float)y1 - gy);
    float wd = (gx - (float)x0) * (gy - (float)y0);

    const float4* S = (const float4*)(X + (size_t)n * HW_ * C_);
    int offA = (y0 * W_ + x0) * 8;
    int offB = (y1 * W_ + x0) * 8;
    int offC = (y0 * W_ + x1) * 8;
    int offD = (y1 * W_ + x1) * 8;

    // 8 independent loads — issue all before consuming (MLP=8).
    float4 va0 = __ldg(&S[offA + cg]);
    float4 vb0 = __ldg(&S[offB + cg]);
    float4 vc0 = __ldg(&S[offC + cg]);
    float4 vd0 = __ldg(&S[offD + cg]);
    float4 va1 = __ldg(&S[offA + cg + 4]);
    float4 vb1 = __ldg(&S[offB + cg + 4]);
    float4 vc1 = __ldg(&S[offC + cg + 4]);
    float4 vd1 = __ldg(&S[offD + cg + 4]);

    float4 r0, r1;
    r0.x = wa * va0.x + wb * vb0.x + wc * vc0.x + wd * vd0.x;
    r0.y = wa * va0.y + wb * vb0.y + wc * vc0.y + wd * vd0.y;
    r0.z = wa * va0.z + wb * vb0.z + wc * vc0.z + wd * vd0.z;
    r0.w = wa * va0.w + wb * vb0.w + wc * vc0.w + wd * vd0.w;
    r1.x = wa * va1.x + wb * vb1.x + wc * vc1.x + wd * vd1.x;
    r1.y = wa * va1.y + wb * vb1.y + wc * vc1.y + wd * vd1.y;
    r1.z = wa * va1.z + wb * vb1.z + wc * vc1.z + wd * vd1.z;
    r1.w = wa * va1.w + wb * vb1.w + wc * vc1.w + wd * vd1.w;

    float4* O = (float4*)out + (size_t)pid * 8;
    O[cg]     = r0;
    O[cg + 4] = r1;
}

extern "C" void kernel_launch(void* const* d_in, const int* in_sizes, int n_in,
                              void* d_out, int out_size)
{
    const float* X     = (const float*)d_in[0];
    const float* theta = (const float*)d_in[1];
    float* out         = (float*)d_out;

    // total threads = N*H*W*4 = 8,388,608
    int threads = 256;
    int blocks = (N_ * HW_ * 4) / threads;   // 32768
    st_kernel<<<blocks, threads>>>(X, theta, out);
}

// round 4
// speedup vs baseline: 1.1989x; 1.0984x over previous
#include <cuda_runtime.h>

// InducingLocationsSpatialTransform: bilinear affine warp
// X: (N=512, H=64, W=64, C=32) f32, theta: (N, 6) f32 -> out: (N,H,W,C) f32
//
// Layout: 8 lanes per pixel (full 128B-line coalescing for every gather and
// store -> minimal L1 wavefronts: 4 read + 1 write per pixel), 2 adjacent
// pixels per thread (pid = 2q, 2q+1 share n, y; x differs by 1 so the affine
// math amortizes). 8 independent gather loads in flight per thread.

#define N_ 512
#define H_ 64
#define W_ 64
#define C_ 32
#define HW_ (H_ * W_)

__global__ __launch_bounds__(256) void st_kernel(
    const float* __restrict__ X,
    const float* __restrict__ theta,
    float* __restrict__ out)
{
    int tid = blockIdx.x * blockDim.x + threadIdx.x;
    int q   = tid >> 3;        // pixel-pair id; handles pixels 2q, 2q+1
    int cg  = tid & 7;         // float4 group within the 32 channels

    int pid0 = q << 1;         // even pixel
    int n = pid0 >> 12;        // image index (same for both pixels)
    int p = pid0 & 4095;
    int y = p >> 6;
    int x = p & 63;            // even; x+1 stays in the same row

    const float* th = theta + n * 6;
    float t0 = __ldg(th + 0), t1 = __ldg(th + 1), t2 = __ldg(th + 2);
    float t3 = __ldg(th + 3), t4 = __ldg(th + 4), t5 = __ldg(th + 5);

    const float step = 2.0f / 63.0f;
    float xt = -1.0f + (float)x * step;
    float yt = -1.0f + (float)y * step;

    // Pixel 0 source coords
    float gxs0 = t0 * xt + t1 * yt + t2;
    float gys0 = t3 * xt + t4 * yt + t5;
    float gx0 = (float)W_ * (gxs0 + 1.0f) * 0.5f;
    float gy0 = (float)H_ * (gys0 + 1.0f) * 0.5f;
    // Pixel 1 = pixel 0 shifted by one grid step in x
    float gx1 = gx0 + (float)W_ * 0.5f * (t0 * step);
    float gy1 = gy0 + (float)H_ * 0.5f * (t3 * step);

    // ---- pixel 0 corners/weights ----
    float fx0 = floorf(gx0), fy0 = floorf(gy0);
    int ax0 = min(max((int)fx0,     0), W_ - 1);
    int ax1 = min(max((int)fx0 + 1, 0), W_ - 1);
    int ay0 = min(max((int)fy0,     0), H_ - 1);
    int ay1 = min(max((int)fy0 + 1, 0), H_ - 1);
    float wa0 = ((float)ax1 - gx0) * ((float)ay1 - gy0);
    float wb0 = ((float)ax1 - gx0) * (gy0 - (float)ay0);
    float wc0 = (gx0 - (float)ax0) * ((float)ay1 - gy0);
    float wd0 = (gx0 - (float)ax0) * (gy0 - (float)ay0);

    // ---- pixel 1 corners/weights ----
    float fx1 = floorf(gx1), fy1 = floorf(gy1);
    int bx0 = min(max((int)fx1,     0), W_ - 1);
    int bx1 = min(max((int)fx1 + 1, 0), W_ - 1);
    int by0 = min(max((int)fy1,     0), H_ - 1);
    int by1 = min(max((int)fy1 + 1, 0), H_ - 1);
    float wa1 = ((float)bx1 - gx1) * ((float)by1 - gy1);
    float wb1 = ((float)bx1 - gx1) * (gy1 - (float)by0);
    float wc1 = (gx1 - (float)bx0) * ((float)by1 - gy1);
    float wd1 = (gx1 - (float)bx0) * (gy1 - (float)by0);

    const float4* S = (const float4*)(X + (size_t)n * HW_ * C_);

    // 8 independent full-line-coalesced loads (MLP=8)
    float4 va0 = __ldg(&S[(ay0 * W_ + ax0) * 8 + cg]);
    float4 vb0 = __ldg(&S[(ay1 * W_ + ax0) * 8 + cg]);
    float4 vc0 = __ldg(&S[(ay0 * W_ + ax1) * 8 + cg]);
    float4 vd0 = __ldg(&S[(ay1 * W_ + ax1) * 8 + cg]);
    float4 va1 = __ldg(&S[(by0 * W_ + bx0) * 8 + cg]);
    float4 vb1 = __ldg(&S[(by1 * W_ + bx0) * 8 + cg]);
    float4 vc1 = __ldg(&S[(by0 * W_ + bx1) * 8 + cg]);
    float4 vd1 = __ldg(&S[(by1 * W_ + bx1) * 8 + cg]);

    float4 r0, r1;
    r0.x = wa0 * va0.x + wb0 * vb0.x + wc0 * vc0.x + wd0 * vd0.x;
    r0.y = wa0 * va0.y + wb0 * vb0.y + wc0 * vc0.y + wd0 * vd0.y;
    r0.z = wa0 * va0.z + wb0 * vb0.z + wc0 * vc0.z + wd0 * vd0.z;
    r0.w = wa0 * va0.w + wb0 * vb0.w + wc0 * vc0.w + wd0 * vd0.w;
    r1.x = wa1 * va1.x + wb1 * vb1.x + wc1 * vc1.x + wd1 * vd1.x;
    r1.y = wa1 * va1.y + wb1 * vb1.y + wc1 * vc1.y + wd1 * vd1.y;
    r1.z = wa1 * va1.z + wb1 * vb1.z + wc1 * vc1.z + wd1 * vd1.z;
    r1.w = wa1 * va1.w + wb1 * vb1.w + wc1 * vc1.w + wd1 * vd1.w;

    float4* O = (float4*)out + (size_t)pid0 * 8;
    O[cg]     = r0;   // pixel 2q   : full-line coalesced across 8 lanes
    O[8 + cg] = r1;   // pixel 2q+1
}

extern "C" void kernel_launch(void* const* d_in, const int* in_sizes, int n_in,
                              void* d_out, int out_size)
{
    const float* X     = (const float*)d_in[0];
    const float* theta = (const float*)d_in[1];
    float* out         = (float*)d_out;

    // total threads = N*H*W/2 * 8 = 8,388,608
    int threads = 256;
    int blocks = (N_ * HW_ * 4) / threads;   // 32768
    st_kernel<<<blocks, threads>>>(X, theta, out);
}